// round 1
// baseline (speedup 1.0000x reference)
#include <cuda_runtime.h>
#include <math.h>

#define NHEAD 16
#define NKV   4
#define DH    64
#define BATCH 2
#define SEQ   2048
#define MTOK  (BATCH*SEQ)     // 4096
#define DM    1024

// Scratch (static device globals -- no allocation allowed)
__device__ float g_Q[(size_t)MTOK * NHEAD * DH];   // 16 MB
__device__ float g_K[(size_t)MTOK * NKV   * DH];   // 4 MB
__device__ float g_V[(size_t)MTOK * NKV   * DH];   // 4 MB
__device__ float g_C[(size_t)MTOK * NHEAD * DH];   // 16 MB

// ---------------------------------------------------------------------------
// Generic tiled fp32 GEMM: C[M,N] = A[M,K] @ B[K,N], all row-major.
// BM=BN=64, BK=16, 256 threads, 4x4 outputs per thread.
// M,N multiples of 64; K multiple of 16 (true for all our shapes).
// ---------------------------------------------------------------------------
__global__ __launch_bounds__(256) void gemm64_kernel(
    const float* __restrict__ A, const float* __restrict__ Bw,
    float* __restrict__ C, int M, int N, int K)
{
    const int BM = 64, BN = 64, BK = 16;
    __shared__ float As[BM][BK];      // [m][k] -- conflict-free write, broadcast read
    __shared__ float Bs[BK][BN + 1];  // [k][n]

    int bm = blockIdx.y * BM;
    int bn = blockIdx.x * BN;
    int tid = threadIdx.x;
    int tr = (tid >> 4) << 2;   // row base 0..60
    int tc = (tid & 15) << 2;   // col base 0..60

    float acc[4][4] = {};

    for (int k0 = 0; k0 < K; k0 += BK) {
        // Load A tile: 64x16 = 1024 elems, 4 per thread, coalesced 64B rows
        #pragma unroll
        for (int i = 0; i < 4; i++) {
            int idx = tid + i * 256;
            int m = idx >> 4, kk = idx & 15;
            As[m][kk] = A[(size_t)(bm + m) * K + (k0 + kk)];
        }
        // Load B tile: 16x64, coalesced 256B rows
        #pragma unroll
        for (int i = 0; i < 4; i++) {
            int idx = tid + i * 256;
            int kk = idx >> 6, n = idx & 63;
            Bs[kk][n] = Bw[(size_t)(k0 + kk) * N + (bn + n)];
        }
        __syncthreads();

        #pragma unroll
        for (int kk = 0; kk < BK; kk++) {
            float a[4], b[4];
            #pragma unroll
            for (int i = 0; i < 4; i++) a[i] = As[tr + i][kk];
            #pragma unroll
            for (int j = 0; j < 4; j++) b[j] = Bs[kk][tc + j];
            #pragma unroll
            for (int i = 0; i < 4; i++)
                #pragma unroll
                for (int j = 0; j < 4; j++)
                    acc[i][j] = fmaf(a[i], b[j], acc[i][j]);
        }
        __syncthreads();
    }

    #pragma unroll
    for (int i = 0; i < 4; i++)
        #pragma unroll
        for (int j = 0; j < 4; j++)
            C[(size_t)(bm + tr + i) * N + (bn + tc + j)] = acc[i][j];
}

// ---------------------------------------------------------------------------
// RoPE in-place on Q [MTOK, NHEAD*DH] and K [MTOK, NKV*DH].
// Matches reference: inv_freq[i] = 10000^(-2i/64) = 10^(-i/8), angle = s*inv_freq,
// out[d]     = x[d]*cos - x[d+32]*sin   (d < 32)
// out[d+32]  = x[d+32]*cos + x[d]*sin
// ---------------------------------------------------------------------------
__global__ void rope_kernel(float* __restrict__ Q, float* __restrict__ K)
{
    const int totq = MTOK * NHEAD * 32;
    const int totk = MTOK * NKV * 32;
    int idx = blockIdx.x * blockDim.x + threadIdx.x;

    if (idx < totq) {
        int i   = idx & 31;
        int h   = (idx >> 5) % NHEAD;
        int tok = idx / (32 * NHEAD);
        int s   = tok % SEQ;
        float invf = exp10f(-(float)i * 0.125f);
        float ang  = (float)s * invf;
        float c = cosf(ang), sn = sinf(ang);
        float* p = Q + (size_t)tok * (NHEAD * DH) + h * DH;
        float x0 = p[i], x1 = p[i + 32];
        p[i]      = x0 * c - x1 * sn;
        p[i + 32] = x1 * c + x0 * sn;
    } else if (idx < totq + totk) {
        int j   = idx - totq;
        int i   = j & 31;
        int h   = (j >> 5) % NKV;
        int tok = j / (32 * NKV);
        int s   = tok % SEQ;
        float invf = exp10f(-(float)i * 0.125f);
        float ang  = (float)s * invf;
        float c = cosf(ang), sn = sinf(ang);
        float* p = K + (size_t)tok * (NKV * DH) + h * DH;
        float x0 = p[i], x1 = p[i + 32];
        p[i]      = x0 * c - x1 * sn;
        p[i + 32] = x1 * c + x0 * sn;
    }
}

// ---------------------------------------------------------------------------
// Flash attention, fp32, causal, GQA (4 Q-heads share each KV-head).
// Grid: (SEQ/64, NHEAD, BATCH). Block: 256 threads.
// Thread (ty = tid/64 in 0..3, tx = tid%64): owns d-column tx for 16 q-rows
// (r = ty + 4*rr). Online softmax with row state in smem.
// Dynamic smem: Qs,Ks,Vs,Ps each 64x65 fp32 + 3*64 row state = 67,328 B.
// ---------------------------------------------------------------------------
#define TQ 64
#define TK 64
#define ATTN_SMEM_BYTES ((4 * TQ * (TK + 1) + 3 * TQ) * (int)sizeof(float))

__global__ __launch_bounds__(256) void attn_kernel(
    const float* __restrict__ Q, const float* __restrict__ K,
    const float* __restrict__ V, float* __restrict__ C)
{
    extern __shared__ float sm[];
    float* Qs   = sm;                       // [64][65]
    float* Ks   = Qs + TQ * (DH + 1);       // [64][65]
    float* Vs   = Ks + TK * (DH + 1);       // [64][65]
    float* Ps   = Vs + TK * (DH + 1);       // [64][65]
    float* mrow = Ps + TQ * (TK + 1);
    float* lrow = mrow + TQ;
    float* crow = lrow + TQ;

    int qt = blockIdx.x;
    int h  = blockIdx.y;
    int b  = blockIdx.z;
    int kh = h / (NHEAD / NKV);

    int tid = threadIdx.x;
    int tx  = tid & 63;      // d-column / kv-column
    int ty  = tid >> 6;      // 0..3

    // Load Q tile
    const float* Qg = Q + ((size_t)(b * SEQ + qt * TQ)) * (NHEAD * DH) + h * DH;
    for (int i = tid; i < TQ * DH; i += 256) {
        int r = i >> 6, d = i & 63;
        Qs[r * (DH + 1) + d] = Qg[(size_t)r * (NHEAD * DH) + d];
    }
    if (tid < TQ) { mrow[tid] = -1e30f; lrow[tid] = 0.0f; }

    float acc[16];
    #pragma unroll
    for (int i = 0; i < 16; i++) acc[i] = 0.0f;
    __syncthreads();

    int nkt = qt + 1;   // causal: kv tiles 0..qt
    for (int kt = 0; kt < nkt; kt++) {
        const float* Kg = K + ((size_t)(b * SEQ + kt * TK)) * (NKV * DH) + kh * DH;
        const float* Vg = V + ((size_t)(b * SEQ + kt * TK)) * (NKV * DH) + kh * DH;
        for (int i = tid; i < TK * DH; i += 256) {
            int r = i >> 6, d = i & 63;
            Ks[r * (DH + 1) + d] = Kg[(size_t)r * (NKV * DH) + d];
            Vs[r * (DH + 1) + d] = Vg[(size_t)r * (NKV * DH) + d];
        }
        __syncthreads();

        // Phase A: scores S[r][tx] = 0.125 * dot(Qs[r], Ks[tx])
        bool diag = (kt == qt);
        #pragma unroll
        for (int rr = 0; rr < 16; rr++) {
            int r = ty + rr * 4;
            float s = 0.0f;
            #pragma unroll
            for (int d = 0; d < DH; d++)
                s = fmaf(Qs[r * (DH + 1) + d], Ks[tx * (DH + 1) + d], s);
            s *= 0.125f;
            if (diag && tx > r) s = -1e30f;
            Ps[r * (TK + 1) + tx] = s;
        }
        __syncthreads();

        // Phase B: per-row online-softmax update (one thread per row)
        if (tid < TQ) {
            int r = tid;
            float m = mrow[r];
            float mx = m;
            #pragma unroll 8
            for (int j = 0; j < TK; j++) mx = fmaxf(mx, Ps[r * (TK + 1) + j]);
            float corr = __expf(m - mx);
            float sum = 0.0f;
            #pragma unroll 8
            for (int j = 0; j < TK; j++) {
                float p = __expf(Ps[r * (TK + 1) + j] - mx);
                Ps[r * (TK + 1) + j] = p;
                sum += p;
            }
            mrow[r] = mx;
            lrow[r] = lrow[r] * corr + sum;
            crow[r] = corr;
        }
        __syncthreads();

        // Phase C: acc[r][tx] = acc*corr + sum_j P[r][j] * V[j][tx]
        #pragma unroll
        for (int rr = 0; rr < 16; rr++) {
            int r = ty + rr * 4;
            float a = acc[rr] * crow[r];
            #pragma unroll
            for (int j = 0; j < TK; j++)
                a = fmaf(Ps[r * (TK + 1) + j], Vs[j * (DH + 1) + tx], a);
            acc[rr] = a;
        }
        __syncthreads();
    }

    // Write ctx: layout [b*S+s, h*64+d] matches the reference's
    // transpose(0,2,1,3).reshape(B,S,1024)
    float* Cg = C + ((size_t)(b * SEQ + qt * TQ)) * (NHEAD * DH) + h * DH;
    #pragma unroll
    for (int rr = 0; rr < 16; rr++) {
        int r = ty + rr * 4;
        Cg[(size_t)r * (NHEAD * DH) + tx] = acc[rr] / lrow[r];
    }
}

// ---------------------------------------------------------------------------
// Launch
// ---------------------------------------------------------------------------
extern "C" void kernel_launch(void* const* d_in, const int* in_sizes, int n_in,
                              void* d_out, int out_size)
{
    const float* x  = (const float*)d_in[0];
    const float* Wq = (const float*)d_in[1];
    const float* Wk = (const float*)d_in[2];
    const float* Wv = (const float*)d_in[3];
    const float* Wo = (const float*)d_in[4];
    float* out = (float*)d_out;

    float *pQ, *pK, *pV, *pC;
    cudaGetSymbolAddress((void**)&pQ, g_Q);
    cudaGetSymbolAddress((void**)&pK, g_K);
    cudaGetSymbolAddress((void**)&pV, g_V);
    cudaGetSymbolAddress((void**)&pC, g_C);

    // QKV projections
    {
        dim3 gq(DM / 64, MTOK / 64);
        gemm64_kernel<<<gq, 256>>>(x, Wq, pQ, MTOK, NHEAD * DH, DM);
        dim3 gk((NKV * DH) / 64, MTOK / 64);
        gemm64_kernel<<<gk, 256>>>(x, Wk, pK, MTOK, NKV * DH, DM);
        gemm64_kernel<<<gk, 256>>>(x, Wv, pV, MTOK, NKV * DH, DM);
    }

    // RoPE (in place on Q and K)
    {
        int total = MTOK * NHEAD * 32 + MTOK * NKV * 32;
        int blocks = (total + 255) / 256;
        rope_kernel<<<blocks, 256>>>(pQ, pK);
    }

    // Flash attention
    {
        cudaFuncSetAttribute(attn_kernel,
                             cudaFuncAttributeMaxDynamicSharedMemorySize,
                             ATTN_SMEM_BYTES);
        dim3 ga(SEQ / TQ, NHEAD, BATCH);
        attn_kernel<<<ga, 256, ATTN_SMEM_BYTES>>>(pQ, pK, pV, pC);
    }

    // Output projection
    {
        dim3 go(DM / 64, MTOK / 64);
        gemm64_kernel<<<go, 256>>>(pC, Wo, out, MTOK, DM, DM);
    }
}

// round 3
// speedup vs baseline: 1.2784x; 1.2784x over previous
#include <cuda_runtime.h>
#include <cuda_bf16.h>
#include <math.h>
#include <cstdint>

#define NHEAD 16
#define NKV   4
#define DH    64
#define BATCH 2
#define SEQ   2048
#define MTOK  (BATCH*SEQ)     // 4096
#define DM    1024
#define NQKV  1536            // 1024(Q) + 256(K) + 256(V)
#define K3    (3*DM)          // 3072 stacked-K

// ---------------------------------------------------------------------------
// Scratch (static device globals -- no allocation allowed)
// ---------------------------------------------------------------------------
__device__ __nv_bfloat16 g_x3[(size_t)MTOK * K3];      // [hi | lo | hi]  24 MB
__device__ __nv_bfloat16 g_Wc3[(size_t)NQKV * K3];     // [N][hi | hi | lo] 9 MB
__device__ __nv_bfloat16 g_Wo3[(size_t)DM * K3];       // 6 MB
__device__ __nv_bfloat16 g_C3[(size_t)MTOK * K3];      // ctx stacked 24 MB
__device__ float g_QKV[(size_t)MTOK * NQKV];           // 24 MB
__device__ float g_C[(size_t)MTOK * DM];               // 16 MB ctx

// ---------------------------------------------------------------------------
// Portable PTX helpers (sm_80-class: cp.async / ldmatrix / mma.sync)
// ---------------------------------------------------------------------------
__device__ __forceinline__ uint32_t smem_u32(const void* p) {
    return (uint32_t)__cvta_generic_to_shared(p);
}
__device__ __forceinline__ void cp_async16(uint32_t saddr, const void* gaddr) {
    asm volatile("cp.async.cg.shared.global [%0], [%1], 16;" :: "r"(saddr), "l"(gaddr));
}
__device__ __forceinline__ void cp_commit() {
    asm volatile("cp.async.commit_group;" ::: "memory");
}
template<int N>
__device__ __forceinline__ void cp_wait() {
    asm volatile("cp.async.wait_group %0;" :: "n"(N) : "memory");
}
__device__ __forceinline__ void ldmatrix_x4(uint32_t& r0, uint32_t& r1,
                                            uint32_t& r2, uint32_t& r3, uint32_t a) {
    asm volatile("ldmatrix.sync.aligned.m8n8.x4.shared.b16 {%0,%1,%2,%3}, [%4];"
                 : "=r"(r0), "=r"(r1), "=r"(r2), "=r"(r3) : "r"(a));
}
__device__ __forceinline__ void mma_bf16(float* c, uint32_t a0, uint32_t a1,
                                         uint32_t a2, uint32_t a3,
                                         uint32_t b0, uint32_t b1) {
    asm volatile("mma.sync.aligned.m16n8k16.row.col.f32.bf16.bf16.f32 "
                 "{%0,%1,%2,%3}, {%4,%5,%6,%7}, {%8,%9}, {%0,%1,%2,%3};"
                 : "+f"(c[0]), "+f"(c[1]), "+f"(c[2]), "+f"(c[3])
                 : "r"(a0), "r"(a1), "r"(a2), "r"(a3), "r"(b0), "r"(b1));
}

// ---------------------------------------------------------------------------
// Prep: split fp32 x -> stacked [hi|lo|hi] bf16 rows
// ---------------------------------------------------------------------------
__global__ void split3_rows(const float* __restrict__ in,
                            __nv_bfloat16* __restrict__ out, int M, int Kd)
{
    int n = M * Kd;
    for (int i = blockIdx.x * blockDim.x + threadIdx.x; i < n; i += gridDim.x * blockDim.x) {
        int m = i / Kd, k = i % Kd;
        float v = in[i];
        __nv_bfloat16 h = __float2bfloat16(v);
        __nv_bfloat16 l = __float2bfloat16(v - __bfloat162float(h));
        size_t base = (size_t)m * (3 * Kd);
        out[base + k]          = h;
        out[base + Kd + k]     = l;
        out[base + 2 * Kd + k] = h;
    }
}

// W[Kdim, Ndim] row-major -> out rows [rowoff+n][3*Kdim] as [hi | hi | lo]
__global__ void transpose_split3(const float* __restrict__ W,
                                 __nv_bfloat16* __restrict__ out,
                                 int Kdim, int Ndim, int rowoff)
{
    __shared__ float t[32][33];
    int n0 = blockIdx.x * 32, k0 = blockIdx.y * 32;
    int tx = threadIdx.x, ty = threadIdx.y;
    #pragma unroll
    for (int i = 0; i < 32; i += 8)
        t[ty + i][tx] = W[(size_t)(k0 + ty + i) * Ndim + (n0 + tx)];
    __syncthreads();
    #pragma unroll
    for (int i = 0; i < 32; i += 8) {
        float v = t[tx][ty + i];
        __nv_bfloat16 h = __float2bfloat16(v);
        __nv_bfloat16 l = __float2bfloat16(v - __bfloat162float(h));
        size_t base = (size_t)(rowoff + n0 + ty + i) * (3 * Kdim) + (k0 + tx);
        out[base]             = h;
        out[base + Kdim]      = h;
        out[base + 2 * Kdim]  = l;
    }
}

// ---------------------------------------------------------------------------
// bf16 tensor-core GEMM via mma.sync: C[M,N] = A3[M,Kg] @ B3[N,Kg]^T
// CTA tile 128x128, BK=32, 8 warps (warp tile 32x64), cp.async double buffer.
// Smem rows padded to 40 bf16 (80B) -> ldmatrix 8-row phases conflict-free.
// ---------------------------------------------------------------------------
#define BM 128
#define BN 128
#define BKK 32
#define LDS_ROW 40   // elements

__global__ __launch_bounds__(256) void mma_gemm(
    const __nv_bfloat16* __restrict__ A, const __nv_bfloat16* __restrict__ B,
    float* __restrict__ C, int M, int N, int Kg)
{
    __shared__ __nv_bfloat16 As[2][BM * LDS_ROW];
    __shared__ __nv_bfloat16 Bs[2][BN * LDS_ROW];

    int tid = threadIdx.x;
    int lane = tid & 31;
    int wid = tid >> 5;
    int wm = wid & 3;          // 0..3 : 32-row band
    int wn = wid >> 2;         // 0..1 : 64-col band
    int m0 = blockIdx.y * BM;
    int n0 = blockIdx.x * BN;

    // cp.async chunk mapping: 512 16B-chunks per tile, 2 per thread
    int r0 = (tid + 0)   >> 2, c0 = (tid + 0)   & 3;
    int r1 = (tid + 256) >> 2, c1 = (tid + 256) & 3;

    const __nv_bfloat16* Ag = A + (size_t)m0 * Kg;
    const __nv_bfloat16* Bg = B + (size_t)n0 * Kg;

    float acc[2][8][4];
    #pragma unroll
    for (int i = 0; i < 2; i++)
        #pragma unroll
        for (int j = 0; j < 8; j++)
            #pragma unroll
            for (int q = 0; q < 4; q++) acc[i][j][q] = 0.0f;

    const int nk = Kg / BKK;

    // prologue: stage 0
    {
        uint32_t sa = smem_u32(&As[0][0]);
        uint32_t sb = smem_u32(&Bs[0][0]);
        cp_async16(sa + (r0 * LDS_ROW + c0 * 8) * 2, Ag + (size_t)r0 * Kg + c0 * 8);
        cp_async16(sa + (r1 * LDS_ROW + c1 * 8) * 2, Ag + (size_t)r1 * Kg + c1 * 8);
        cp_async16(sb + (r0 * LDS_ROW + c0 * 8) * 2, Bg + (size_t)r0 * Kg + c0 * 8);
        cp_async16(sb + (r1 * LDS_ROW + c1 * 8) * 2, Bg + (size_t)r1 * Kg + c1 * 8);
        cp_commit();
    }

    // ldmatrix lane addressing (element offsets within tile)
    int a_row = wm * 32 + (lane & 15);          // + mi*16
    int a_colp = (lane >> 4) * 8;               // + k16*16
    int b_row = wn * 64 + (lane & 7) + ((lane >> 4) << 3);   // + ni2*16
    int b_colp = ((lane >> 3) & 1) * 8;         // + k16*16

    for (int kt = 0; kt < nk; kt++) {
        int buf = kt & 1;
        if (kt + 1 < nk) {
            int nb = buf ^ 1;
            int kg = (kt + 1) * BKK;
            uint32_t sa = smem_u32(&As[nb][0]);
            uint32_t sb = smem_u32(&Bs[nb][0]);
            cp_async16(sa + (r0 * LDS_ROW + c0 * 8) * 2, Ag + (size_t)r0 * Kg + kg + c0 * 8);
            cp_async16(sa + (r1 * LDS_ROW + c1 * 8) * 2, Ag + (size_t)r1 * Kg + kg + c1 * 8);
            cp_async16(sb + (r0 * LDS_ROW + c0 * 8) * 2, Bg + (size_t)r0 * Kg + kg + c0 * 8);
            cp_async16(sb + (r1 * LDS_ROW + c1 * 8) * 2, Bg + (size_t)r1 * Kg + kg + c1 * 8);
            cp_commit();
            cp_wait<1>();
        } else {
            cp_wait<0>();
        }
        __syncthreads();

        uint32_t sa = smem_u32(&As[buf][0]);
        uint32_t sb = smem_u32(&Bs[buf][0]);
        #pragma unroll
        for (int k16 = 0; k16 < 2; k16++) {
            uint32_t af[2][4];
            #pragma unroll
            for (int mi = 0; mi < 2; mi++) {
                uint32_t addr = sa + (((a_row + mi * 16) * LDS_ROW) + k16 * 16 + a_colp) * 2;
                ldmatrix_x4(af[mi][0], af[mi][1], af[mi][2], af[mi][3], addr);
            }
            uint32_t bf[4][4];
            #pragma unroll
            for (int ni2 = 0; ni2 < 4; ni2++) {
                uint32_t addr = sb + (((b_row + ni2 * 16) * LDS_ROW) + k16 * 16 + b_colp) * 2;
                ldmatrix_x4(bf[ni2][0], bf[ni2][1], bf[ni2][2], bf[ni2][3], addr);
            }
            #pragma unroll
            for (int mi = 0; mi < 2; mi++)
                #pragma unroll
                for (int ni = 0; ni < 8; ni++) {
                    uint32_t bb0 = bf[ni >> 1][(ni & 1) * 2];
                    uint32_t bb1 = bf[ni >> 1][(ni & 1) * 2 + 1];
                    mma_bf16(acc[mi][ni], af[mi][0], af[mi][1], af[mi][2], af[mi][3], bb0, bb1);
                }
        }
        __syncthreads();
    }

    // Epilogue: direct global float2 stores
    int cr = lane >> 2;
    int cc = (lane & 3) * 2;
    #pragma unroll
    for (int mi = 0; mi < 2; mi++) {
        #pragma unroll
        for (int ni = 0; ni < 8; ni++) {
            int row = m0 + wm * 32 + mi * 16 + cr;
            int col = n0 + wn * 64 + ni * 8 + cc;
            float2* p0 = (float2*)&C[(size_t)row * N + col];
            float2* p1 = (float2*)&C[(size_t)(row + 8) * N + col];
            *p0 = make_float2(acc[mi][ni][0], acc[mi][ni][1]);
            *p1 = make_float2(acc[mi][ni][2], acc[mi][ni][3]);
        }
    }
}

// ---------------------------------------------------------------------------
// RoPE in-place on QKV buffer [MTOK, 1536]
// ---------------------------------------------------------------------------
__global__ void rope_kernel(float* __restrict__ QKV)
{
    const int totq = MTOK * NHEAD * 32;
    const int totk = MTOK * NKV * 32;
    int idx = blockIdx.x * blockDim.x + threadIdx.x;

    float* p;
    int i, s;
    if (idx < totq) {
        i = idx & 31;
        int h   = (idx >> 5) % NHEAD;
        int tok = idx / (32 * NHEAD);
        s = tok % SEQ;
        p = QKV + (size_t)tok * NQKV + h * DH;
    } else if (idx < totq + totk) {
        int j = idx - totq;
        i = j & 31;
        int h   = (j >> 5) % NKV;
        int tok = j / (32 * NKV);
        s = tok % SEQ;
        p = QKV + (size_t)tok * NQKV + 1024 + h * DH;
    } else return;

    float invf = exp10f(-(float)i * 0.125f);
    float ang  = (float)s * invf;
    float c = cosf(ang), sn = sinf(ang);
    float x0 = p[i], x1 = p[i + 32];
    p[i]      = x0 * c - x1 * sn;
    p[i + 32] = x1 * c + x0 * sn;
}

// ---------------------------------------------------------------------------
// Flash attention, fp32, causal, GQA. Reads Q/K/V from combined QKV buffer.
// ---------------------------------------------------------------------------
#define TQ 64
#define TK 64
#define ATTN_SMEM_BYTES ((4 * TQ * (TK + 1) + 3 * TQ) * (int)sizeof(float))

__global__ __launch_bounds__(256) void attn_kernel(
    const float* __restrict__ QKV, float* __restrict__ C)
{
    extern __shared__ float sm[];
    float* Qs   = sm;
    float* Ks   = Qs + TQ * (DH + 1);
    float* Vs   = Ks + TK * (DH + 1);
    float* Ps   = Vs + TK * (DH + 1);
    float* mrow = Ps + TQ * (TK + 1);
    float* lrow = mrow + TQ;
    float* crow = lrow + TQ;

    int qt = blockIdx.x;
    int h  = blockIdx.y;
    int b  = blockIdx.z;
    int kh = h / (NHEAD / NKV);

    int tid = threadIdx.x;
    int tx  = tid & 63;
    int ty  = tid >> 6;

    const float* Qg = QKV + ((size_t)(b * SEQ + qt * TQ)) * NQKV + h * DH;
    for (int i = tid; i < TQ * DH; i += 256) {
        int r = i >> 6, d = i & 63;
        Qs[r * (DH + 1) + d] = Qg[(size_t)r * NQKV + d];
    }
    if (tid < TQ) { mrow[tid] = -1e30f; lrow[tid] = 0.0f; }

    float acc[16];
    #pragma unroll
    for (int i = 0; i < 16; i++) acc[i] = 0.0f;
    __syncthreads();

    int nkt = qt + 1;
    for (int kt = 0; kt < nkt; kt++) {
        const float* Kg = QKV + ((size_t)(b * SEQ + kt * TK)) * NQKV + 1024 + kh * DH;
        const float* Vg = QKV + ((size_t)(b * SEQ + kt * TK)) * NQKV + 1280 + kh * DH;
        for (int i = tid; i < TK * DH; i += 256) {
            int r = i >> 6, d = i & 63;
            Ks[r * (DH + 1) + d] = Kg[(size_t)r * NQKV + d];
            Vs[r * (DH + 1) + d] = Vg[(size_t)r * NQKV + d];
        }
        __syncthreads();

        bool diag = (kt == qt);
        #pragma unroll
        for (int rr = 0; rr < 16; rr++) {
            int r = ty + rr * 4;
            float s = 0.0f;
            #pragma unroll
            for (int d = 0; d < DH; d++)
                s = fmaf(Qs[r * (DH + 1) + d], Ks[tx * (DH + 1) + d], s);
            s *= 0.125f;
            if (diag && tx > r) s = -1e30f;
            Ps[r * (TK + 1) + tx] = s;
        }
        __syncthreads();

        if (tid < TQ) {
            int r = tid;
            float m = mrow[r];
            float mx = m;
            #pragma unroll 8
            for (int j = 0; j < TK; j++) mx = fmaxf(mx, Ps[r * (TK + 1) + j]);
            float corr = __expf(m - mx);
            float sum = 0.0f;
            #pragma unroll 8
            for (int j = 0; j < TK; j++) {
                float p = __expf(Ps[r * (TK + 1) + j] - mx);
                Ps[r * (TK + 1) + j] = p;
                sum += p;
            }
            mrow[r] = mx;
            lrow[r] = lrow[r] * corr + sum;
            crow[r] = corr;
        }
        __syncthreads();

        #pragma unroll
        for (int rr = 0; rr < 16; rr++) {
            int r = ty + rr * 4;
            float a = acc[rr] * crow[r];
            #pragma unroll
            for (int j = 0; j < TK; j++)
                a = fmaf(Ps[r * (TK + 1) + j], Vs[j * (DH + 1) + tx], a);
            acc[rr] = a;
        }
        __syncthreads();
    }

    float* Cg = C + ((size_t)(b * SEQ + qt * TQ)) * (NHEAD * DH) + h * DH;
    #pragma unroll
    for (int rr = 0; rr < 16; rr++) {
        int r = ty + rr * 4;
        Cg[(size_t)r * (NHEAD * DH) + tx] = acc[rr] / lrow[r];
    }
}

// ---------------------------------------------------------------------------
// Launch
// ---------------------------------------------------------------------------
extern "C" void kernel_launch(void* const* d_in, const int* in_sizes, int n_in,
                              void* d_out, int out_size)
{
    const float* x  = (const float*)d_in[0];
    const float* Wq = (const float*)d_in[1];
    const float* Wk = (const float*)d_in[2];
    const float* Wv = (const float*)d_in[3];
    const float* Wo = (const float*)d_in[4];
    float* out = (float*)d_out;

    __nv_bfloat16 *px3, *pWc3, *pWo3, *pC3;
    float *pQKV, *pC;
    cudaGetSymbolAddress((void**)&px3, g_x3);
    cudaGetSymbolAddress((void**)&pWc3, g_Wc3);
    cudaGetSymbolAddress((void**)&pWo3, g_Wo3);
    cudaGetSymbolAddress((void**)&pC3, g_C3);
    cudaGetSymbolAddress((void**)&pQKV, g_QKV);
    cudaGetSymbolAddress((void**)&pC, g_C);

    // Weight transpose + stacked split
    {
        dim3 blk(32, 8);
        transpose_split3<<<dim3(DM / 32, DM / 32), blk>>>(Wq, pWc3, DM, DM, 0);
        transpose_split3<<<dim3(256 / 32, DM / 32), blk>>>(Wk, pWc3, DM, 256, 1024);
        transpose_split3<<<dim3(256 / 32, DM / 32), blk>>>(Wv, pWc3, DM, 256, 1280);
        transpose_split3<<<dim3(DM / 32, DM / 32), blk>>>(Wo, pWo3, DM, DM, 0);
    }

    // x -> stacked bf16 [hi|lo|hi]
    split3_rows<<<2048, 256>>>(x, px3, MTOK, DM);

    // QKV projection: one tensor-core GEMM [4096,1536] with K'=3072
    {
        dim3 g(NQKV / BN, MTOK / BM);
        mma_gemm<<<g, 256>>>(px3, pWc3, pQKV, MTOK, NQKV, K3);
    }

    // RoPE in place on Q and K parts of QKV
    {
        int total = MTOK * NHEAD * 32 + MTOK * NKV * 32;
        rope_kernel<<<(total + 255) / 256, 256>>>(pQKV);
    }

    // Flash attention
    {
        cudaFuncSetAttribute(attn_kernel,
                             cudaFuncAttributeMaxDynamicSharedMemorySize,
                             ATTN_SMEM_BYTES);
        dim3 ga(SEQ / TQ, NHEAD, BATCH);
        attn_kernel<<<ga, 256, ATTN_SMEM_BYTES>>>(pQKV, pC);
    }

    // ctx -> stacked bf16, then output projection GEMM
    split3_rows<<<2048, 256>>>(pC, pC3, MTOK, DM);
    {
        dim3 g(DM / BN, MTOK / BM);
        mma_gemm<<<g, 256>>>(pC3, pWo3, out, MTOK, DM, K3);
    }
}

// round 4
// speedup vs baseline: 4.2743x; 3.3434x over previous
#include <cuda_runtime.h>
#include <cuda_bf16.h>
#include <math.h>
#include <cstdint>

#define NHEAD 16
#define NKV   4
#define DH    64
#define BATCH 2
#define SEQ   2048
#define MTOK  (BATCH*SEQ)     // 4096
#define DM    1024
#define NQKV  1536            // 1024(Q) + 256(K) + 256(V)
#define K3    (3*DM)          // 3072 stacked-K

// ---------------------------------------------------------------------------
// Scratch (static device globals -- no allocation allowed)
// ---------------------------------------------------------------------------
__device__ __nv_bfloat16 g_x3[(size_t)MTOK * K3];      // [hi | lo | hi]  24 MB
__device__ __nv_bfloat16 g_Wc3[(size_t)NQKV * K3];     // [N][hi | hi | lo] 9 MB
__device__ __nv_bfloat16 g_Wo3[(size_t)DM * K3];       // 6 MB
__device__ __nv_bfloat16 g_C3[(size_t)MTOK * K3];      // ctx stacked 24 MB
__device__ float g_QKV[(size_t)MTOK * NQKV];           // 24 MB

// ---------------------------------------------------------------------------
// Portable PTX helpers (sm_80-class: cp.async / ldmatrix / mma.sync)
// ---------------------------------------------------------------------------
__device__ __forceinline__ uint32_t smem_u32(const void* p) {
    return (uint32_t)__cvta_generic_to_shared(p);
}
__device__ __forceinline__ void cp_async16(uint32_t saddr, const void* gaddr) {
    asm volatile("cp.async.cg.shared.global [%0], [%1], 16;" :: "r"(saddr), "l"(gaddr));
}
__device__ __forceinline__ void cp_commit() {
    asm volatile("cp.async.commit_group;" ::: "memory");
}
template<int N>
__device__ __forceinline__ void cp_wait() {
    asm volatile("cp.async.wait_group %0;" :: "n"(N) : "memory");
}
__device__ __forceinline__ void ldmatrix_x4(uint32_t& r0, uint32_t& r1,
                                            uint32_t& r2, uint32_t& r3, uint32_t a) {
    asm volatile("ldmatrix.sync.aligned.m8n8.x4.shared.b16 {%0,%1,%2,%3}, [%4];"
                 : "=r"(r0), "=r"(r1), "=r"(r2), "=r"(r3) : "r"(a));
}
__device__ __forceinline__ void ldmatrix_x4_t(uint32_t& r0, uint32_t& r1,
                                              uint32_t& r2, uint32_t& r3, uint32_t a) {
    asm volatile("ldmatrix.sync.aligned.m8n8.x4.trans.shared.b16 {%0,%1,%2,%3}, [%4];"
                 : "=r"(r0), "=r"(r1), "=r"(r2), "=r"(r3) : "r"(a));
}
__device__ __forceinline__ void mma_bf16(float* c, uint32_t a0, uint32_t a1,
                                         uint32_t a2, uint32_t a3,
                                         uint32_t b0, uint32_t b1) {
    asm volatile("mma.sync.aligned.m16n8k16.row.col.f32.bf16.bf16.f32 "
                 "{%0,%1,%2,%3}, {%4,%5,%6,%7}, {%8,%9}, {%0,%1,%2,%3};"
                 : "+f"(c[0]), "+f"(c[1]), "+f"(c[2]), "+f"(c[3])
                 : "r"(a0), "r"(a1), "r"(a2), "r"(a3), "r"(b0), "r"(b1));
}
__device__ __forceinline__ float ex2(float x) {
    float r; asm("ex2.approx.f32 %0, %1;" : "=f"(r) : "f"(x)); return r;
}
// pack two f32 -> bf16x2 reg (lo = x, hi = y)
__device__ __forceinline__ uint32_t pack_bf2(float x, float y) {
    uint32_t r; asm("cvt.rn.bf16x2.f32 %0, %1, %2;" : "=r"(r) : "f"(y), "f"(x)); return r;
}
__device__ __forceinline__ float bflo_f(uint32_t p) { return __uint_as_float(p << 16); }
__device__ __forceinline__ float bfhi_f(uint32_t p) { return __uint_as_float(p & 0xffff0000u); }

// ---------------------------------------------------------------------------
// Prep: split fp32 x -> stacked [hi|lo|hi] bf16 rows
// ---------------------------------------------------------------------------
__global__ void split3_rows(const float* __restrict__ in,
                            __nv_bfloat16* __restrict__ out, int M, int Kd)
{
    int n = M * Kd;
    for (int i = blockIdx.x * blockDim.x + threadIdx.x; i < n; i += gridDim.x * blockDim.x) {
        int m = i / Kd, k = i % Kd;
        float v = in[i];
        __nv_bfloat16 h = __float2bfloat16(v);
        __nv_bfloat16 l = __float2bfloat16(v - __bfloat162float(h));
        size_t base = (size_t)m * (3 * Kd);
        out[base + k]          = h;
        out[base + Kd + k]     = l;
        out[base + 2 * Kd + k] = h;
    }
}

// W[Kdim, Ndim] row-major -> out rows [rowoff+n][3*Kdim] as [hi | hi | lo]
__global__ void transpose_split3(const float* __restrict__ W,
                                 __nv_bfloat16* __restrict__ out,
                                 int Kdim, int Ndim, int rowoff)
{
    __shared__ float t[32][33];
    int n0 = blockIdx.x * 32, k0 = blockIdx.y * 32;
    int tx = threadIdx.x, ty = threadIdx.y;
    #pragma unroll
    for (int i = 0; i < 32; i += 8)
        t[ty + i][tx] = W[(size_t)(k0 + ty + i) * Ndim + (n0 + tx)];
    __syncthreads();
    #pragma unroll
    for (int i = 0; i < 32; i += 8) {
        float v = t[tx][ty + i];
        __nv_bfloat16 h = __float2bfloat16(v);
        __nv_bfloat16 l = __float2bfloat16(v - __bfloat162float(h));
        size_t base = (size_t)(rowoff + n0 + ty + i) * (3 * Kdim) + (k0 + tx);
        out[base]             = h;
        out[base + Kdim]      = h;
        out[base + 2 * Kdim]  = l;
    }
}

// ---------------------------------------------------------------------------
// bf16 tensor-core GEMM via mma.sync: C[M,N] = A3[M,Kg] @ B3[N,Kg]^T
// ---------------------------------------------------------------------------
#define BM 128
#define BN 128
#define BKK 32
#define LDS_ROW 40   // elements

__global__ __launch_bounds__(256) void mma_gemm(
    const __nv_bfloat16* __restrict__ A, const __nv_bfloat16* __restrict__ B,
    float* __restrict__ C, int M, int N, int Kg)
{
    __shared__ __nv_bfloat16 As[2][BM * LDS_ROW];
    __shared__ __nv_bfloat16 Bs[2][BN * LDS_ROW];

    int tid = threadIdx.x;
    int lane = tid & 31;
    int wid = tid >> 5;
    int wm = wid & 3;
    int wn = wid >> 2;
    int m0 = blockIdx.y * BM;
    int n0 = blockIdx.x * BN;

    int r0 = (tid + 0)   >> 2, c0 = (tid + 0)   & 3;
    int r1 = (tid + 256) >> 2, c1 = (tid + 256) & 3;

    const __nv_bfloat16* Ag = A + (size_t)m0 * Kg;
    const __nv_bfloat16* Bg = B + (size_t)n0 * Kg;

    float acc[2][8][4];
    #pragma unroll
    for (int i = 0; i < 2; i++)
        #pragma unroll
        for (int j = 0; j < 8; j++)
            #pragma unroll
            for (int q = 0; q < 4; q++) acc[i][j][q] = 0.0f;

    const int nk = Kg / BKK;

    {
        uint32_t sa = smem_u32(&As[0][0]);
        uint32_t sb = smem_u32(&Bs[0][0]);
        cp_async16(sa + (r0 * LDS_ROW + c0 * 8) * 2, Ag + (size_t)r0 * Kg + c0 * 8);
        cp_async16(sa + (r1 * LDS_ROW + c1 * 8) * 2, Ag + (size_t)r1 * Kg + c1 * 8);
        cp_async16(sb + (r0 * LDS_ROW + c0 * 8) * 2, Bg + (size_t)r0 * Kg + c0 * 8);
        cp_async16(sb + (r1 * LDS_ROW + c1 * 8) * 2, Bg + (size_t)r1 * Kg + c1 * 8);
        cp_commit();
    }

    int a_row = wm * 32 + (lane & 15);
    int a_colp = (lane >> 4) * 8;
    int b_row = wn * 64 + (lane & 7) + ((lane >> 4) << 3);
    int b_colp = ((lane >> 3) & 1) * 8;

    for (int kt = 0; kt < nk; kt++) {
        int buf = kt & 1;
        if (kt + 1 < nk) {
            int nb = buf ^ 1;
            int kg = (kt + 1) * BKK;
            uint32_t sa = smem_u32(&As[nb][0]);
            uint32_t sb = smem_u32(&Bs[nb][0]);
            cp_async16(sa + (r0 * LDS_ROW + c0 * 8) * 2, Ag + (size_t)r0 * Kg + kg + c0 * 8);
            cp_async16(sa + (r1 * LDS_ROW + c1 * 8) * 2, Ag + (size_t)r1 * Kg + kg + c1 * 8);
            cp_async16(sb + (r0 * LDS_ROW + c0 * 8) * 2, Bg + (size_t)r0 * Kg + kg + c0 * 8);
            cp_async16(sb + (r1 * LDS_ROW + c1 * 8) * 2, Bg + (size_t)r1 * Kg + kg + c1 * 8);
            cp_commit();
            cp_wait<1>();
        } else {
            cp_wait<0>();
        }
        __syncthreads();

        uint32_t sa = smem_u32(&As[buf][0]);
        uint32_t sb = smem_u32(&Bs[buf][0]);
        #pragma unroll
        for (int k16 = 0; k16 < 2; k16++) {
            uint32_t af[2][4];
            #pragma unroll
            for (int mi = 0; mi < 2; mi++) {
                uint32_t addr = sa + (((a_row + mi * 16) * LDS_ROW) + k16 * 16 + a_colp) * 2;
                ldmatrix_x4(af[mi][0], af[mi][1], af[mi][2], af[mi][3], addr);
            }
            uint32_t bfr[4][4];
            #pragma unroll
            for (int ni2 = 0; ni2 < 4; ni2++) {
                uint32_t addr = sb + (((b_row + ni2 * 16) * LDS_ROW) + k16 * 16 + b_colp) * 2;
                ldmatrix_x4(bfr[ni2][0], bfr[ni2][1], bfr[ni2][2], bfr[ni2][3], addr);
            }
            #pragma unroll
            for (int mi = 0; mi < 2; mi++)
                #pragma unroll
                for (int ni = 0; ni < 8; ni++) {
                    uint32_t bb0 = bfr[ni >> 1][(ni & 1) * 2];
                    uint32_t bb1 = bfr[ni >> 1][(ni & 1) * 2 + 1];
                    mma_bf16(acc[mi][ni], af[mi][0], af[mi][1], af[mi][2], af[mi][3], bb0, bb1);
                }
        }
        __syncthreads();
    }

    int cr = lane >> 2;
    int cc = (lane & 3) * 2;
    #pragma unroll
    for (int mi = 0; mi < 2; mi++) {
        #pragma unroll
        for (int ni = 0; ni < 8; ni++) {
            int row = m0 + wm * 32 + mi * 16 + cr;
            int col = n0 + wn * 64 + ni * 8 + cc;
            float2* p0 = (float2*)&C[(size_t)row * N + col];
            float2* p1 = (float2*)&C[(size_t)(row + 8) * N + col];
            *p0 = make_float2(acc[mi][ni][0], acc[mi][ni][1]);
            *p1 = make_float2(acc[mi][ni][2], acc[mi][ni][3]);
        }
    }
}

// ---------------------------------------------------------------------------
// RoPE in-place on QKV buffer [MTOK, 1536]
// ---------------------------------------------------------------------------
__global__ void rope_kernel(float* __restrict__ QKV)
{
    const int totq = MTOK * NHEAD * 32;
    const int totk = MTOK * NKV * 32;
    int idx = blockIdx.x * blockDim.x + threadIdx.x;

    float* p;
    int i, s;
    if (idx < totq) {
        i = idx & 31;
        int h   = (idx >> 5) % NHEAD;
        int tok = idx / (32 * NHEAD);
        s = tok % SEQ;
        p = QKV + (size_t)tok * NQKV + h * DH;
    } else if (idx < totq + totk) {
        int j = idx - totq;
        i = j & 31;
        int h   = (j >> 5) % NKV;
        int tok = j / (32 * NKV);
        s = tok % SEQ;
        p = QKV + (size_t)tok * NQKV + 1024 + h * DH;
    } else return;

    float invf = exp10f(-(float)i * 0.125f);
    float ang  = (float)s * invf;
    float c = cosf(ang), sn = sinf(ang);
    float x0 = p[i], x1 = p[i + 32];
    p[i]      = x0 * c - x1 * sn;
    p[i + 32] = x1 * c + x0 * sn;
}

// ---------------------------------------------------------------------------
// Tensor-core flash attention (mma.sync bf16, hi/lo compensated), causal GQA.
// Grid: (16 qtiles reversed, NHEAD, BATCH). Block 256 (8 warps x 16 q-rows).
// Smem rows padded to 72 bf16 (144B): conflict-free ldmatrix.
// Writes stacked [hi|lo|hi] ctx directly into g_C3.
// ---------------------------------------------------------------------------
#define AROW 72
#define SQ_HI 0
#define SQ_LO (128*AROW*2)
#define SK_HI (2*128*AROW*2)
#define SK_LO (SK_HI + 64*AROW*2)
#define SV_HI (SK_LO + 64*AROW*2)
#define SV_LO (SV_HI + 64*AROW*2)
#define ATTN_SMEM (SV_LO + 64*AROW*2)   // 73728 B

__global__ __launch_bounds__(256) void attn_mma(
    const float* __restrict__ QKV, __nv_bfloat16* __restrict__ C3)
{
    extern __shared__ char smc[];
    uint32_t sb = smem_u32(smc);

    int qt = (int)gridDim.x - 1 - (int)blockIdx.x;
    int h  = blockIdx.y;
    int b  = blockIdx.z;
    int kh = h >> 2;

    int tid  = threadIdx.x;
    int lane = tid & 31;
    int wm   = tid >> 5;          // warp id: rows [wm*16, wm*16+16)

    // --- load Q tile (128 x 64) as hi/lo bf16, rows padded to 72 ---
    {
        const float* Qg = QKV + ((size_t)(b * SEQ + qt * 128)) * NQKV + h * DH;
        #pragma unroll
        for (int it = 0; it < 16; it++) {
            int idx = tid + it * 256;         // 4096 float2
            int r = idx >> 5, dp = idx & 31;  // d = 2*dp
            float2 v = *(const float2*)&Qg[(size_t)r * NQKV + 2 * dp];
            uint32_t hi = pack_bf2(v.x, v.y);
            float2 lo = make_float2(v.x - bflo_f(hi), v.y - bfhi_f(hi));
            uint32_t lp = pack_bf2(lo.x, lo.y);
            uint32_t off = (r * AROW + 2 * dp) * 2;
            *(uint32_t*)(smc + SQ_HI + off) = hi;
            *(uint32_t*)(smc + SQ_LO + off) = lp;
        }
    }

    // ldmatrix lane-address components (byte offsets)
    uint32_t qa_off = (uint32_t)((wm * 16 + (lane & 7) + ((lane >> 3) & 1) * 8) * (AROW * 2)
                                 + (lane >> 4) * 16);
    uint32_t kb_off = (uint32_t)(((lane & 7) + (lane >> 4) * 8) * (AROW * 2)
                                 + ((lane >> 3) & 1) * 16);
    uint32_t vb_off = (uint32_t)(((lane & 7) + ((lane >> 3) & 1) * 8) * (AROW * 2)
                                 + (lane >> 4) * 16);

    float acc[8][4];
    #pragma unroll
    for (int j = 0; j < 8; j++)
        #pragma unroll
        for (int q = 0; q < 4; q++) acc[j][q] = 0.0f;
    float m0 = -1e30f, m1 = -1e30f, l0 = 0.0f, l1 = 0.0f;

    const float SCL = 0.125f * 1.44269504f;
    int row0g = qt * 128 + wm * 16 + (lane >> 2);
    int colbase = 2 * (lane & 3);

    int nkt = 2 * qt + 2;
    for (int kt = 0; kt < nkt; kt++) {
        __syncthreads();
        // --- load K,V tiles (64 x 64 each) hi/lo ---
        {
            const float* Kg = QKV + ((size_t)(b * SEQ + kt * 64)) * NQKV + 1024 + kh * DH;
            const float* Vg = QKV + ((size_t)(b * SEQ + kt * 64)) * NQKV + 1280 + kh * DH;
            #pragma unroll
            for (int it = 0; it < 8; it++) {
                int idx = tid + it * 256;        // 2048 float2
                int r = idx >> 5, dp = idx & 31;
                uint32_t off = (r * AROW + 2 * dp) * 2;
                float2 v = *(const float2*)&Kg[(size_t)r * NQKV + 2 * dp];
                uint32_t hi = pack_bf2(v.x, v.y);
                uint32_t lp = pack_bf2(v.x - bflo_f(hi), v.y - bfhi_f(hi));
                *(uint32_t*)(smc + SK_HI + off) = hi;
                *(uint32_t*)(smc + SK_LO + off) = lp;
                v = *(const float2*)&Vg[(size_t)r * NQKV + 2 * dp];
                hi = pack_bf2(v.x, v.y);
                lp = pack_bf2(v.x - bflo_f(hi), v.y - bfhi_f(hi));
                *(uint32_t*)(smc + SV_HI + off) = hi;
                *(uint32_t*)(smc + SV_LO + off) = lp;
            }
        }
        __syncthreads();

        // --- S = Q K^T (compensated: qh*kh + ql*kh + qh*kl) ---
        float sf[8][4];
        #pragma unroll
        for (int j = 0; j < 8; j++)
            #pragma unroll
            for (int q = 0; q < 4; q++) sf[j][q] = 0.0f;

        #pragma unroll
        for (int t = 0; t < 4; t++) {
            uint32_t qh[4], ql[4];
            ldmatrix_x4(qh[0], qh[1], qh[2], qh[3], sb + SQ_HI + qa_off + t * 32);
            ldmatrix_x4(ql[0], ql[1], ql[2], ql[3], sb + SQ_LO + qa_off + t * 32);
            #pragma unroll
            for (int jj = 0; jj < 4; jj++) {
                uint32_t kmh[4], kml[4];
                uint32_t off = kb_off + jj * 16 * (AROW * 2) + t * 32;
                ldmatrix_x4(kmh[0], kmh[1], kmh[2], kmh[3], sb + SK_HI + off);
                ldmatrix_x4(kml[0], kml[1], kml[2], kml[3], sb + SK_LO + off);
                mma_bf16(sf[2*jj],   qh[0], qh[1], qh[2], qh[3], kmh[0], kmh[1]);
                mma_bf16(sf[2*jj],   ql[0], ql[1], ql[2], ql[3], kmh[0], kmh[1]);
                mma_bf16(sf[2*jj],   qh[0], qh[1], qh[2], qh[3], kml[0], kml[1]);
                mma_bf16(sf[2*jj+1], qh[0], qh[1], qh[2], qh[3], kmh[2], kmh[3]);
                mma_bf16(sf[2*jj+1], ql[0], ql[1], ql[2], ql[3], kmh[2], kmh[3]);
                mma_bf16(sf[2*jj+1], qh[0], qh[1], qh[2], qh[3], kml[2], kml[3]);
            }
        }

        // --- scale + causal mask (exp2 domain) ---
        bool need_mask = (kt * 64 + 63 > qt * 128 + wm * 16);
        if (need_mask) {
            #pragma unroll
            for (int j = 0; j < 8; j++) {
                int c0 = kt * 64 + 8 * j + colbase;
                sf[j][0] = (c0     <= row0g)     ? sf[j][0] * SCL : -1e30f;
                sf[j][1] = (c0 + 1 <= row0g)     ? sf[j][1] * SCL : -1e30f;
                sf[j][2] = (c0     <= row0g + 8) ? sf[j][2] * SCL : -1e30f;
                sf[j][3] = (c0 + 1 <= row0g + 8) ? sf[j][3] * SCL : -1e30f;
            }
        } else {
            #pragma unroll
            for (int j = 0; j < 8; j++)
                #pragma unroll
                for (int q = 0; q < 4; q++) sf[j][q] *= SCL;
        }

        // --- online softmax ---
        float mx0 = m0, mx1 = m1;
        #pragma unroll
        for (int j = 0; j < 8; j++) {
            mx0 = fmaxf(mx0, fmaxf(sf[j][0], sf[j][1]));
            mx1 = fmaxf(mx1, fmaxf(sf[j][2], sf[j][3]));
        }
        mx0 = fmaxf(mx0, __shfl_xor_sync(0xffffffffu, mx0, 1));
        mx0 = fmaxf(mx0, __shfl_xor_sync(0xffffffffu, mx0, 2));
        mx1 = fmaxf(mx1, __shfl_xor_sync(0xffffffffu, mx1, 1));
        mx1 = fmaxf(mx1, __shfl_xor_sync(0xffffffffu, mx1, 2));
        float corr0 = ex2(m0 - mx0);
        float corr1 = ex2(m1 - mx1);
        m0 = mx0; m1 = mx1;

        float ls0 = 0.0f, ls1 = 0.0f;
        #pragma unroll
        for (int j = 0; j < 8; j++) {
            sf[j][0] = ex2(sf[j][0] - mx0);
            sf[j][1] = ex2(sf[j][1] - mx0);
            sf[j][2] = ex2(sf[j][2] - mx1);
            sf[j][3] = ex2(sf[j][3] - mx1);
            ls0 += sf[j][0] + sf[j][1];
            ls1 += sf[j][2] + sf[j][3];
        }
        l0 = l0 * corr0 + ls0;
        l1 = l1 * corr1 + ls1;
        #pragma unroll
        for (int j = 0; j < 8; j++) {
            acc[j][0] *= corr0; acc[j][1] *= corr0;
            acc[j][2] *= corr1; acc[j][3] *= corr1;
        }

        // --- PV (compensated: ph*vh + pl*vh + ph*vl) ---
        #pragma unroll
        for (int t = 0; t < 4; t++) {
            uint32_t aph[4], apl[4];
            {
                float p00 = sf[2*t][0],   p01 = sf[2*t][1];
                float p10 = sf[2*t][2],   p11 = sf[2*t][3];
                float p20 = sf[2*t+1][0], p21 = sf[2*t+1][1];
                float p30 = sf[2*t+1][2], p31 = sf[2*t+1][3];
                aph[0] = pack_bf2(p00, p01);
                aph[1] = pack_bf2(p10, p11);
                aph[2] = pack_bf2(p20, p21);
                aph[3] = pack_bf2(p30, p31);
                apl[0] = pack_bf2(p00 - bflo_f(aph[0]), p01 - bfhi_f(aph[0]));
                apl[1] = pack_bf2(p10 - bflo_f(aph[1]), p11 - bfhi_f(aph[1]));
                apl[2] = pack_bf2(p20 - bflo_f(aph[2]), p21 - bfhi_f(aph[2]));
                apl[3] = pack_bf2(p30 - bflo_f(aph[3]), p31 - bfhi_f(aph[3]));
            }
            #pragma unroll
            for (int jj = 0; jj < 4; jj++) {
                uint32_t vh[4], vl[4];
                uint32_t off = vb_off + t * 16 * (AROW * 2) + jj * 32;
                ldmatrix_x4_t(vh[0], vh[1], vh[2], vh[3], sb + SV_HI + off);
                ldmatrix_x4_t(vl[0], vl[1], vl[2], vl[3], sb + SV_LO + off);
                mma_bf16(acc[2*jj],   aph[0], aph[1], aph[2], aph[3], vh[0], vh[1]);
                mma_bf16(acc[2*jj],   apl[0], apl[1], apl[2], apl[3], vh[0], vh[1]);
                mma_bf16(acc[2*jj],   aph[0], aph[1], aph[2], aph[3], vl[0], vl[1]);
                mma_bf16(acc[2*jj+1], aph[0], aph[1], aph[2], aph[3], vh[2], vh[3]);
                mma_bf16(acc[2*jj+1], apl[0], apl[1], apl[2], apl[3], vh[2], vh[3]);
                mma_bf16(acc[2*jj+1], aph[0], aph[1], aph[2], aph[3], vl[2], vl[3]);
            }
        }
    }

    // --- final normalize + write stacked [hi|lo|hi] ctx into C3 ---
    l0 += __shfl_xor_sync(0xffffffffu, l0, 1);
    l0 += __shfl_xor_sync(0xffffffffu, l0, 2);
    l1 += __shfl_xor_sync(0xffffffffu, l1, 1);
    l1 += __shfl_xor_sync(0xffffffffu, l1, 2);
    float inv0 = 1.0f / l0, inv1 = 1.0f / l1;

    size_t rbase0 = (size_t)(b * SEQ + row0g) * K3;
    size_t rbase1 = rbase0 + 8 * K3;
    int dcol = h * DH + colbase;
    #pragma unroll
    for (int j = 0; j < 8; j++) {
        int d = dcol + 8 * j;
        float v0 = acc[j][0] * inv0, v1 = acc[j][1] * inv0;
        float v2 = acc[j][2] * inv1, v3 = acc[j][3] * inv1;
        uint32_t h0 = pack_bf2(v0, v1);
        uint32_t lo0 = pack_bf2(v0 - bflo_f(h0), v1 - bfhi_f(h0));
        uint32_t h1 = pack_bf2(v2, v3);
        uint32_t lo1 = pack_bf2(v2 - bflo_f(h1), v3 - bfhi_f(h1));
        *(uint32_t*)&C3[rbase0 + d]          = h0;
        *(uint32_t*)&C3[rbase0 + DM + d]     = lo0;
        *(uint32_t*)&C3[rbase0 + 2*DM + d]   = h0;
        *(uint32_t*)&C3[rbase1 + d]          = h1;
        *(uint32_t*)&C3[rbase1 + DM + d]     = lo1;
        *(uint32_t*)&C3[rbase1 + 2*DM + d]   = h1;
    }
}

// ---------------------------------------------------------------------------
// Launch
// ---------------------------------------------------------------------------
extern "C" void kernel_launch(void* const* d_in, const int* in_sizes, int n_in,
                              void* d_out, int out_size)
{
    const float* x  = (const float*)d_in[0];
    const float* Wq = (const float*)d_in[1];
    const float* Wk = (const float*)d_in[2];
    const float* Wv = (const float*)d_in[3];
    const float* Wo = (const float*)d_in[4];
    float* out = (float*)d_out;

    __nv_bfloat16 *px3, *pWc3, *pWo3, *pC3;
    float *pQKV;
    cudaGetSymbolAddress((void**)&px3, g_x3);
    cudaGetSymbolAddress((void**)&pWc3, g_Wc3);
    cudaGetSymbolAddress((void**)&pWo3, g_Wo3);
    cudaGetSymbolAddress((void**)&pC3, g_C3);
    cudaGetSymbolAddress((void**)&pQKV, g_QKV);

    // Weight transpose + stacked split
    {
        dim3 blk(32, 8);
        transpose_split3<<<dim3(DM / 32, DM / 32), blk>>>(Wq, pWc3, DM, DM, 0);
        transpose_split3<<<dim3(256 / 32, DM / 32), blk>>>(Wk, pWc3, DM, 256, 1024);
        transpose_split3<<<dim3(256 / 32, DM / 32), blk>>>(Wv, pWc3, DM, 256, 1280);
        transpose_split3<<<dim3(DM / 32, DM / 32), blk>>>(Wo, pWo3, DM, DM, 0);
    }

    // x -> stacked bf16 [hi|lo|hi]
    split3_rows<<<2048, 256>>>(x, px3, MTOK, DM);

    // QKV projection GEMM
    {
        dim3 g(NQKV / BN, MTOK / BM);
        mma_gemm<<<g, 256>>>(px3, pWc3, pQKV, MTOK, NQKV, K3);
    }

    // RoPE in place on Q and K parts of QKV
    {
        int total = MTOK * NHEAD * 32 + MTOK * NKV * 32;
        rope_kernel<<<(total + 255) / 256, 256>>>(pQKV);
    }

    // Tensor-core flash attention (writes stacked ctx into g_C3)
    {
        cudaFuncSetAttribute(attn_mma,
                             cudaFuncAttributeMaxDynamicSharedMemorySize,
                             ATTN_SMEM);
        dim3 ga(SEQ / 128, NHEAD, BATCH);
        attn_mma<<<ga, 256, ATTN_SMEM>>>(pQKV, pC3);
    }

    // Output projection GEMM
    {
        dim3 g(DM / BN, MTOK / BM);
        mma_gemm<<<g, 256>>>(pC3, pWo3, out, MTOK, DM, K3);
    }
}

// round 5
// speedup vs baseline: 4.2883x; 1.0033x over previous
#include <cuda_runtime.h>
#include <cuda_bf16.h>
#include <math.h>
#include <cstdint>

#define NHEAD 16
#define NKV   4
#define DH    64
#define BATCH 2
#define SEQ   2048
#define MTOK  (BATCH*SEQ)     // 4096
#define DM    1024
#define NQKV  1536            // 1024(Q) + 256(K) + 256(V)
#define K3    (3*DM)          // 3072 stacked-K

// ---------------------------------------------------------------------------
// Scratch (static device globals -- no allocation allowed)
// ---------------------------------------------------------------------------
__device__ __nv_bfloat16 g_x3[(size_t)MTOK * K3];      // [hi | lo | hi]  24 MB
__device__ __nv_bfloat16 g_Wc3[(size_t)NQKV * K3];     // [N][hi | hi | lo] 9 MB
__device__ __nv_bfloat16 g_Wo3[(size_t)DM * K3];       // 6 MB
__device__ __nv_bfloat16 g_C3[(size_t)MTOK * K3];      // ctx stacked 24 MB
__device__ __nv_bfloat16 g_Qhi[(size_t)MTOK * NQKV];   // QKV hi plane 12 MB
__device__ __nv_bfloat16 g_Qlo[(size_t)MTOK * NQKV];   // QKV lo plane 12 MB

// ---------------------------------------------------------------------------
// Portable PTX helpers (sm_80-class: cp.async / ldmatrix / mma.sync)
// ---------------------------------------------------------------------------
__device__ __forceinline__ uint32_t smem_u32(const void* p) {
    return (uint32_t)__cvta_generic_to_shared(p);
}
__device__ __forceinline__ void cp_async16(uint32_t saddr, const void* gaddr) {
    asm volatile("cp.async.cg.shared.global [%0], [%1], 16;" :: "r"(saddr), "l"(gaddr));
}
__device__ __forceinline__ void cp_commit() {
    asm volatile("cp.async.commit_group;" ::: "memory");
}
template<int N>
__device__ __forceinline__ void cp_wait() {
    asm volatile("cp.async.wait_group %0;" :: "n"(N) : "memory");
}
__device__ __forceinline__ void ldmatrix_x4(uint32_t& r0, uint32_t& r1,
                                            uint32_t& r2, uint32_t& r3, uint32_t a) {
    asm volatile("ldmatrix.sync.aligned.m8n8.x4.shared.b16 {%0,%1,%2,%3}, [%4];"
                 : "=r"(r0), "=r"(r1), "=r"(r2), "=r"(r3) : "r"(a));
}
__device__ __forceinline__ void ldmatrix_x4_t(uint32_t& r0, uint32_t& r1,
                                              uint32_t& r2, uint32_t& r3, uint32_t a) {
    asm volatile("ldmatrix.sync.aligned.m8n8.x4.trans.shared.b16 {%0,%1,%2,%3}, [%4];"
                 : "=r"(r0), "=r"(r1), "=r"(r2), "=r"(r3) : "r"(a));
}
__device__ __forceinline__ void mma_bf16(float* c, uint32_t a0, uint32_t a1,
                                         uint32_t a2, uint32_t a3,
                                         uint32_t b0, uint32_t b1) {
    asm volatile("mma.sync.aligned.m16n8k16.row.col.f32.bf16.bf16.f32 "
                 "{%0,%1,%2,%3}, {%4,%5,%6,%7}, {%8,%9}, {%0,%1,%2,%3};"
                 : "+f"(c[0]), "+f"(c[1]), "+f"(c[2]), "+f"(c[3])
                 : "r"(a0), "r"(a1), "r"(a2), "r"(a3), "r"(b0), "r"(b1));
}
__device__ __forceinline__ float ex2(float x) {
    float r; asm("ex2.approx.f32 %0, %1;" : "=f"(r) : "f"(x)); return r;
}
// pack two f32 -> bf16x2 reg (lo = x, hi = y)
__device__ __forceinline__ uint32_t pack_bf2(float x, float y) {
    uint32_t r; asm("cvt.rn.bf16x2.f32 %0, %1, %2;" : "=r"(r) : "f"(y), "f"(x)); return r;
}
__device__ __forceinline__ float bflo_f(uint32_t p) { return __uint_as_float(p << 16); }
__device__ __forceinline__ float bfhi_f(uint32_t p) { return __uint_as_float(p & 0xffff0000u); }

// ---------------------------------------------------------------------------
// Prep: split fp32 x -> stacked [hi|lo|hi] bf16 rows
// ---------------------------------------------------------------------------
__global__ void split3_rows(const float* __restrict__ in,
                            __nv_bfloat16* __restrict__ out, int M, int Kd)
{
    int n = M * Kd;
    for (int i = blockIdx.x * blockDim.x + threadIdx.x; i < n; i += gridDim.x * blockDim.x) {
        int m = i / Kd, k = i % Kd;
        float v = in[i];
        __nv_bfloat16 h = __float2bfloat16(v);
        __nv_bfloat16 l = __float2bfloat16(v - __bfloat162float(h));
        size_t base = (size_t)m * (3 * Kd);
        out[base + k]          = h;
        out[base + Kd + k]     = l;
        out[base + 2 * Kd + k] = h;
    }
}

// W[Kdim, Ndim] row-major -> out rows [rowoff+n][3*Kdim] as [hi | hi | lo]
__global__ void transpose_split3(const float* __restrict__ W,
                                 __nv_bfloat16* __restrict__ out,
                                 int Kdim, int Ndim, int rowoff)
{
    __shared__ float t[32][33];
    int n0 = blockIdx.x * 32, k0 = blockIdx.y * 32;
    int tx = threadIdx.x, ty = threadIdx.y;
    #pragma unroll
    for (int i = 0; i < 32; i += 8)
        t[ty + i][tx] = W[(size_t)(k0 + ty + i) * Ndim + (n0 + tx)];
    __syncthreads();
    #pragma unroll
    for (int i = 0; i < 32; i += 8) {
        float v = t[tx][ty + i];
        __nv_bfloat16 h = __float2bfloat16(v);
        __nv_bfloat16 l = __float2bfloat16(v - __bfloat162float(h));
        size_t base = (size_t)(rowoff + n0 + ty + i) * (3 * Kdim) + (k0 + tx);
        out[base]             = h;
        out[base + Kdim]      = h;
        out[base + 2 * Kdim]  = l;
    }
}

// ---------------------------------------------------------------------------
// bf16 tensor-core GEMM, 3-stage cp.async pipeline.
// OUT_MODE 0: C fp32.  OUT_MODE 1: bf16 hi/lo planes.
// ---------------------------------------------------------------------------
#define BM 128
#define BN 128
#define BKK 32
#define LDS_ROW 40   // elements
#define GEMM_BUF (BM * LDS_ROW * 2)        // bytes per A (or B) stage
#define GEMM_SMEM (6 * GEMM_BUF)           // 3 stages x (A+B) = 61440

template<int OUT_MODE>
__global__ __launch_bounds__(256, 2) void mma_gemm(
    const __nv_bfloat16* __restrict__ A, const __nv_bfloat16* __restrict__ B,
    float* __restrict__ C, __nv_bfloat16* __restrict__ Chi,
    __nv_bfloat16* __restrict__ Clo, int M, int N, int Kg)
{
    extern __shared__ char gsm[];
    // layout: A0 A1 A2 B0 B1 B2
    uint32_t sabase = smem_u32(gsm);

    int tid = threadIdx.x;
    int lane = tid & 31;
    int wid = tid >> 5;
    int wm = wid & 3;
    int wn = wid >> 2;
    int m0 = blockIdx.y * BM;
    int n0 = blockIdx.x * BN;

    int r0 = (tid + 0)   >> 2, c0 = (tid + 0)   & 3;
    int r1 = (tid + 256) >> 2, c1 = (tid + 256) & 3;

    const __nv_bfloat16* Ag = A + (size_t)m0 * Kg;
    const __nv_bfloat16* Bg = B + (size_t)n0 * Kg;

    float acc[2][8][4];
    #pragma unroll
    for (int i = 0; i < 2; i++)
        #pragma unroll
        for (int j = 0; j < 8; j++)
            #pragma unroll
            for (int q = 0; q < 4; q++) acc[i][j][q] = 0.0f;

    const int nk = Kg / BKK;

    auto issue = [&](int kt, int s) {
        int kg = kt * BKK;
        uint32_t sa = sabase + s * GEMM_BUF;
        uint32_t sb = sabase + (3 + s) * GEMM_BUF;
        cp_async16(sa + (r0 * LDS_ROW + c0 * 8) * 2, Ag + (size_t)r0 * Kg + kg + c0 * 8);
        cp_async16(sa + (r1 * LDS_ROW + c1 * 8) * 2, Ag + (size_t)r1 * Kg + kg + c1 * 8);
        cp_async16(sb + (r0 * LDS_ROW + c0 * 8) * 2, Bg + (size_t)r0 * Kg + kg + c0 * 8);
        cp_async16(sb + (r1 * LDS_ROW + c1 * 8) * 2, Bg + (size_t)r1 * Kg + kg + c1 * 8);
        cp_commit();
    };

    issue(0, 0);
    issue(1, 1);

    int a_row = wm * 32 + (lane & 15);
    int a_colp = (lane >> 4) * 8;
    int b_row = wn * 64 + (lane & 7) + ((lane >> 4) << 3);
    int b_colp = ((lane >> 3) & 1) * 8;

    int buf = 0;
    for (int kt = 0; kt < nk; kt++) {
        if (kt + 2 < nk) { issue(kt + 2, (kt + 2) % 3); cp_wait<2>(); }
        else if (kt + 1 < nk) { cp_wait<1>(); }
        else { cp_wait<0>(); }
        __syncthreads();

        uint32_t sa = sabase + buf * GEMM_BUF;
        uint32_t sb = sabase + (3 + buf) * GEMM_BUF;
        #pragma unroll
        for (int k16 = 0; k16 < 2; k16++) {
            uint32_t af[2][4];
            #pragma unroll
            for (int mi = 0; mi < 2; mi++) {
                uint32_t addr = sa + (((a_row + mi * 16) * LDS_ROW) + k16 * 16 + a_colp) * 2;
                ldmatrix_x4(af[mi][0], af[mi][1], af[mi][2], af[mi][3], addr);
            }
            uint32_t bfr[4][4];
            #pragma unroll
            for (int ni2 = 0; ni2 < 4; ni2++) {
                uint32_t addr = sb + (((b_row + ni2 * 16) * LDS_ROW) + k16 * 16 + b_colp) * 2;
                ldmatrix_x4(bfr[ni2][0], bfr[ni2][1], bfr[ni2][2], bfr[ni2][3], addr);
            }
            #pragma unroll
            for (int mi = 0; mi < 2; mi++)
                #pragma unroll
                for (int ni = 0; ni < 8; ni++) {
                    uint32_t bb0 = bfr[ni >> 1][(ni & 1) * 2];
                    uint32_t bb1 = bfr[ni >> 1][(ni & 1) * 2 + 1];
                    mma_bf16(acc[mi][ni], af[mi][0], af[mi][1], af[mi][2], af[mi][3], bb0, bb1);
                }
        }
        __syncthreads();
        buf = (buf + 1 == 3) ? 0 : buf + 1;
    }

    int cr = lane >> 2;
    int cc = (lane & 3) * 2;
    #pragma unroll
    for (int mi = 0; mi < 2; mi++) {
        #pragma unroll
        for (int ni = 0; ni < 8; ni++) {
            int row = m0 + wm * 32 + mi * 16 + cr;
            int col = n0 + wn * 64 + ni * 8 + cc;
            if (OUT_MODE == 0) {
                *(float2*)&C[(size_t)row * N + col] =
                    make_float2(acc[mi][ni][0], acc[mi][ni][1]);
                *(float2*)&C[(size_t)(row + 8) * N + col] =
                    make_float2(acc[mi][ni][2], acc[mi][ni][3]);
            } else {
                float v0 = acc[mi][ni][0], v1 = acc[mi][ni][1];
                float v2 = acc[mi][ni][2], v3 = acc[mi][ni][3];
                uint32_t h0 = pack_bf2(v0, v1);
                uint32_t l0 = pack_bf2(v0 - bflo_f(h0), v1 - bfhi_f(h0));
                uint32_t h1 = pack_bf2(v2, v3);
                uint32_t l1 = pack_bf2(v2 - bflo_f(h1), v3 - bfhi_f(h1));
                *(uint32_t*)&Chi[(size_t)row * N + col] = h0;
                *(uint32_t*)&Clo[(size_t)row * N + col] = l0;
                *(uint32_t*)&Chi[(size_t)(row + 8) * N + col] = h1;
                *(uint32_t*)&Clo[(size_t)(row + 8) * N + col] = l1;
            }
        }
    }
}

// ---------------------------------------------------------------------------
// RoPE in-place on bf16 hi/lo planes [MTOK, 1536]: Q heads 0..15 (cols h*64),
// K heads 0..3 (cols 1024+h*64).
// ---------------------------------------------------------------------------
__global__ void rope_kernel(__nv_bfloat16* __restrict__ hi,
                            __nv_bfloat16* __restrict__ lo)
{
    const int tot = MTOK * 20 * 32;
    int idx = blockIdx.x * blockDim.x + threadIdx.x;
    if (idx >= tot) return;

    int i    = idx & 31;
    int hh   = (idx >> 5) % 20;
    int tok  = idx / (32 * 20);
    int s    = tok % SEQ;
    int col  = (hh < 16) ? hh * DH : 1024 + (hh - 16) * DH;
    size_t base = (size_t)tok * NQKV + col;

    float invf = exp10f(-(float)i * 0.125f);
    float ang  = (float)s * invf;
    float c = cosf(ang), sn = sinf(ang);

    float x0 = __bfloat162float(hi[base + i])      + __bfloat162float(lo[base + i]);
    float x1 = __bfloat162float(hi[base + i + 32]) + __bfloat162float(lo[base + i + 32]);
    float y0 = x0 * c - x1 * sn;
    float y1 = x1 * c + x0 * sn;

    __nv_bfloat16 h0 = __float2bfloat16(y0);
    __nv_bfloat16 h1 = __float2bfloat16(y1);
    hi[base + i]      = h0;
    lo[base + i]      = __float2bfloat16(y0 - __bfloat162float(h0));
    hi[base + i + 32] = h1;
    lo[base + i + 32] = __float2bfloat16(y1 - __bfloat162float(h1));
}

// ---------------------------------------------------------------------------
// Tensor-core flash attention, bf16 hi/lo plane inputs via cp.async,
// double-buffered KV pipeline. Causal GQA.
// Grid: (16 qtiles reversed, NHEAD, BATCH). Block 256 (8 warps x 16 q-rows).
// Smem rows 72 bf16 (144B). Writes stacked [hi|lo|hi] ctx into g_C3.
// ---------------------------------------------------------------------------
#define AROW 72
#define ROWB (AROW*2)          // 144 bytes per row
#define SQ_HI 0
#define SQ_LO (128*ROWB)       // 18432
#define SKV0  (2*128*ROWB)     // 36864
#define KVSTG (4*64*ROWB)      // 36864 per stage (Khi,Klo,Vhi,Vlo)
#define ATTN_SMEM (SKV0 + 2*KVSTG)   // 110592

__global__ __launch_bounds__(256) void attn_mma(
    const __nv_bfloat16* __restrict__ Phi, const __nv_bfloat16* __restrict__ Plo,
    __nv_bfloat16* __restrict__ C3)
{
    extern __shared__ char smc[];
    uint32_t sb = smem_u32(smc);

    int qt = (int)gridDim.x - 1 - (int)blockIdx.x;
    int h  = blockIdx.y;
    int b  = blockIdx.z;
    int kh = h >> 2;

    int tid  = threadIdx.x;
    int lane = tid & 31;
    int wm   = tid >> 5;

    const int kcol = 1024 + kh * DH;
    const int vcol = 1280 + kh * DH;

    // --- issue Q tile + KV tile 0 as group 0 ---
    {
        // Q: 2048 chunks (plane, r, c)
        #pragma unroll
        for (int it = 0; it < 8; it++) {
            int idx = tid + it * 256;
            int pl = idx >> 10;
            int j = idx & 1023;
            int r = j >> 3, c = j & 7;
            const __nv_bfloat16* src = (pl ? Plo : Phi)
                + (size_t)(b * SEQ + qt * 128 + r) * NQKV + h * DH + c * 8;
            uint32_t dst = sb + (pl ? SQ_LO : SQ_HI) + r * ROWB + c * 16;
            cp_async16(dst, src);
        }
        // KV tile 0 into stage 0
        #pragma unroll
        for (int it = 0; it < 8; it++) {
            int idx = tid + it * 256;
            int sel = idx >> 9;             // 0 Khi,1 Klo,2 Vhi,3 Vlo
            int j = idx & 511;
            int r = j >> 3, c = j & 7;
            const __nv_bfloat16* base = (sel & 1) ? Plo : Phi;
            int colb = (sel < 2) ? kcol : vcol;
            const __nv_bfloat16* src = base + (size_t)(b * SEQ + r) * NQKV + colb + c * 8;
            uint32_t dst = sb + SKV0 + sel * (64 * ROWB) + r * ROWB + c * 16;
            cp_async16(dst, src);
        }
        cp_commit();
    }

    uint32_t qa_off = (uint32_t)((wm * 16 + (lane & 7) + ((lane >> 3) & 1) * 8) * ROWB
                                 + (lane >> 4) * 16);
    uint32_t kb_off = (uint32_t)(((lane & 7) + (lane >> 4) * 8) * ROWB
                                 + ((lane >> 3) & 1) * 16);
    uint32_t vb_off = (uint32_t)(((lane & 7) + ((lane >> 3) & 1) * 8) * ROWB
                                 + (lane >> 4) * 16);

    float acc[8][4];
    #pragma unroll
    for (int j = 0; j < 8; j++)
        #pragma unroll
        for (int q = 0; q < 4; q++) acc[j][q] = 0.0f;
    float m0 = -1e30f, m1 = -1e30f, l0 = 0.0f, l1 = 0.0f;

    const float SCL = 0.125f * 1.44269504f;
    int row0g = qt * 128 + wm * 16 + (lane >> 2);
    int colbase = 2 * (lane & 3);

    int nkt = 2 * qt + 2;
    for (int kt = 0; kt < nkt; kt++) {
        // prefetch next KV tile
        if (kt + 1 < nkt) {
            int stg = (kt + 1) & 1;
            #pragma unroll
            for (int it = 0; it < 8; it++) {
                int idx = tid + it * 256;
                int sel = idx >> 9;
                int j = idx & 511;
                int r = j >> 3, c = j & 7;
                const __nv_bfloat16* base = (sel & 1) ? Plo : Phi;
                int colb = (sel < 2) ? kcol : vcol;
                const __nv_bfloat16* src = base
                    + (size_t)(b * SEQ + (kt + 1) * 64 + r) * NQKV + colb + c * 8;
                uint32_t dst = sb + SKV0 + stg * KVSTG + sel * (64 * ROWB) + r * ROWB + c * 16;
                cp_async16(dst, src);
            }
            cp_commit();
            cp_wait<1>();
        } else {
            cp_wait<0>();
        }
        __syncthreads();

        uint32_t kvb = sb + SKV0 + (kt & 1) * KVSTG;
        uint32_t skh = kvb, skl = kvb + 64 * ROWB;
        uint32_t svh = kvb + 2 * 64 * ROWB, svl = kvb + 3 * 64 * ROWB;

        // --- S = Q K^T (qh*kh + ql*kh + qh*kl) ---
        float sf[8][4];
        #pragma unroll
        for (int j = 0; j < 8; j++)
            #pragma unroll
            for (int q = 0; q < 4; q++) sf[j][q] = 0.0f;

        #pragma unroll
        for (int t = 0; t < 4; t++) {
            uint32_t qh[4], ql[4];
            ldmatrix_x4(qh[0], qh[1], qh[2], qh[3], sb + SQ_HI + qa_off + t * 32);
            ldmatrix_x4(ql[0], ql[1], ql[2], ql[3], sb + SQ_LO + qa_off + t * 32);
            #pragma unroll
            for (int jj = 0; jj < 4; jj++) {
                uint32_t kmh[4], kml[4];
                uint32_t off = kb_off + jj * 16 * ROWB + t * 32;
                ldmatrix_x4(kmh[0], kmh[1], kmh[2], kmh[3], skh + off);
                ldmatrix_x4(kml[0], kml[1], kml[2], kml[3], skl + off);
                mma_bf16(sf[2*jj],   qh[0], qh[1], qh[2], qh[3], kmh[0], kmh[1]);
                mma_bf16(sf[2*jj],   ql[0], ql[1], ql[2], ql[3], kmh[0], kmh[1]);
                mma_bf16(sf[2*jj],   qh[0], qh[1], qh[2], qh[3], kml[0], kml[1]);
                mma_bf16(sf[2*jj+1], qh[0], qh[1], qh[2], qh[3], kmh[2], kmh[3]);
                mma_bf16(sf[2*jj+1], ql[0], ql[1], ql[2], ql[3], kmh[2], kmh[3]);
                mma_bf16(sf[2*jj+1], qh[0], qh[1], qh[2], qh[3], kml[2], kml[3]);
            }
        }

        // --- scale + causal mask ---
        bool need_mask = (kt * 64 + 63 > qt * 128 + wm * 16);
        if (need_mask) {
            #pragma unroll
            for (int j = 0; j < 8; j++) {
                int c0 = kt * 64 + 8 * j + colbase;
                sf[j][0] = (c0     <= row0g)     ? sf[j][0] * SCL : -1e30f;
                sf[j][1] = (c0 + 1 <= row0g)     ? sf[j][1] * SCL : -1e30f;
                sf[j][2] = (c0     <= row0g + 8) ? sf[j][2] * SCL : -1e30f;
                sf[j][3] = (c0 + 1 <= row0g + 8) ? sf[j][3] * SCL : -1e30f;
            }
        } else {
            #pragma unroll
            for (int j = 0; j < 8; j++)
                #pragma unroll
                for (int q = 0; q < 4; q++) sf[j][q] *= SCL;
        }

        // --- online softmax ---
        float mx0 = m0, mx1 = m1;
        #pragma unroll
        for (int j = 0; j < 8; j++) {
            mx0 = fmaxf(mx0, fmaxf(sf[j][0], sf[j][1]));
            mx1 = fmaxf(mx1, fmaxf(sf[j][2], sf[j][3]));
        }
        mx0 = fmaxf(mx0, __shfl_xor_sync(0xffffffffu, mx0, 1));
        mx0 = fmaxf(mx0, __shfl_xor_sync(0xffffffffu, mx0, 2));
        mx1 = fmaxf(mx1, __shfl_xor_sync(0xffffffffu, mx1, 1));
        mx1 = fmaxf(mx1, __shfl_xor_sync(0xffffffffu, mx1, 2));
        float corr0 = ex2(m0 - mx0);
        float corr1 = ex2(m1 - mx1);
        m0 = mx0; m1 = mx1;

        float ls0 = 0.0f, ls1 = 0.0f;
        #pragma unroll
        for (int j = 0; j < 8; j++) {
            sf[j][0] = ex2(sf[j][0] - mx0);
            sf[j][1] = ex2(sf[j][1] - mx0);
            sf[j][2] = ex2(sf[j][2] - mx1);
            sf[j][3] = ex2(sf[j][3] - mx1);
            ls0 += sf[j][0] + sf[j][1];
            ls1 += sf[j][2] + sf[j][3];
        }
        l0 = l0 * corr0 + ls0;
        l1 = l1 * corr1 + ls1;
        #pragma unroll
        for (int j = 0; j < 8; j++) {
            acc[j][0] *= corr0; acc[j][1] *= corr0;
            acc[j][2] *= corr1; acc[j][3] *= corr1;
        }

        // --- PV (ph*vh + pl*vh + ph*vl) ---
        #pragma unroll
        for (int t = 0; t < 4; t++) {
            uint32_t aph[4], apl[4];
            {
                float p00 = sf[2*t][0],   p01 = sf[2*t][1];
                float p10 = sf[2*t][2],   p11 = sf[2*t][3];
                float p20 = sf[2*t+1][0], p21 = sf[2*t+1][1];
                float p30 = sf[2*t+1][2], p31 = sf[2*t+1][3];
                aph[0] = pack_bf2(p00, p01);
                aph[1] = pack_bf2(p10, p11);
                aph[2] = pack_bf2(p20, p21);
                aph[3] = pack_bf2(p30, p31);
                apl[0] = pack_bf2(p00 - bflo_f(aph[0]), p01 - bfhi_f(aph[0]));
                apl[1] = pack_bf2(p10 - bflo_f(aph[1]), p11 - bfhi_f(aph[1]));
                apl[2] = pack_bf2(p20 - bflo_f(aph[2]), p21 - bfhi_f(aph[2]));
                apl[3] = pack_bf2(p30 - bflo_f(aph[3]), p31 - bfhi_f(aph[3]));
            }
            #pragma unroll
            for (int jj = 0; jj < 4; jj++) {
                uint32_t vh[4], vl[4];
                uint32_t off = vb_off + t * 16 * ROWB + jj * 32;
                ldmatrix_x4_t(vh[0], vh[1], vh[2], vh[3], svh + off);
                ldmatrix_x4_t(vl[0], vl[1], vl[2], vl[3], svl + off);
                mma_bf16(acc[2*jj],   aph[0], aph[1], aph[2], aph[3], vh[0], vh[1]);
                mma_bf16(acc[2*jj],   apl[0], apl[1], apl[2], apl[3], vh[0], vh[1]);
                mma_bf16(acc[2*jj],   aph[0], aph[1], aph[2], aph[3], vl[0], vl[1]);
                mma_bf16(acc[2*jj+1], aph[0], aph[1], aph[2], aph[3], vh[2], vh[3]);
                mma_bf16(acc[2*jj+1], apl[0], apl[1], apl[2], apl[3], vh[2], vh[3]);
                mma_bf16(acc[2*jj+1], aph[0], aph[1], aph[2], aph[3], vl[2], vl[3]);
            }
        }
        __syncthreads();
    }

    // --- final normalize + write stacked [hi|lo|hi] ctx into C3 ---
    l0 += __shfl_xor_sync(0xffffffffu, l0, 1);
    l0 += __shfl_xor_sync(0xffffffffu, l0, 2);
    l1 += __shfl_xor_sync(0xffffffffu, l1, 1);
    l1 += __shfl_xor_sync(0xffffffffu, l1, 2);
    float inv0 = 1.0f / l0, inv1 = 1.0f / l1;

    size_t rbase0 = (size_t)(b * SEQ + row0g) * K3;
    size_t rbase1 = rbase0 + 8 * K3;
    int dcol = h * DH + colbase;
    #pragma unroll
    for (int j = 0; j < 8; j++) {
        int d = dcol + 8 * j;
        float v0 = acc[j][0] * inv0, v1 = acc[j][1] * inv0;
        float v2 = acc[j][2] * inv1, v3 = acc[j][3] * inv1;
        uint32_t h0 = pack_bf2(v0, v1);
        uint32_t lo0 = pack_bf2(v0 - bflo_f(h0), v1 - bfhi_f(h0));
        uint32_t h1 = pack_bf2(v2, v3);
        uint32_t lo1 = pack_bf2(v2 - bflo_f(h1), v3 - bfhi_f(h1));
        *(uint32_t*)&C3[rbase0 + d]          = h0;
        *(uint32_t*)&C3[rbase0 + DM + d]     = lo0;
        *(uint32_t*)&C3[rbase0 + 2*DM + d]   = h0;
        *(uint32_t*)&C3[rbase1 + d]          = h1;
        *(uint32_t*)&C3[rbase1 + DM + d]     = lo1;
        *(uint32_t*)&C3[rbase1 + 2*DM + d]   = h1;
    }
}

// ---------------------------------------------------------------------------
// Launch
// ---------------------------------------------------------------------------
extern "C" void kernel_launch(void* const* d_in, const int* in_sizes, int n_in,
                              void* d_out, int out_size)
{
    const float* x  = (const float*)d_in[0];
    const float* Wq = (const float*)d_in[1];
    const float* Wk = (const float*)d_in[2];
    const float* Wv = (const float*)d_in[3];
    const float* Wo = (const float*)d_in[4];
    float* out = (float*)d_out;

    __nv_bfloat16 *px3, *pWc3, *pWo3, *pC3, *pQhi, *pQlo;
    cudaGetSymbolAddress((void**)&px3, g_x3);
    cudaGetSymbolAddress((void**)&pWc3, g_Wc3);
    cudaGetSymbolAddress((void**)&pWo3, g_Wo3);
    cudaGetSymbolAddress((void**)&pC3, g_C3);
    cudaGetSymbolAddress((void**)&pQhi, g_Qhi);
    cudaGetSymbolAddress((void**)&pQlo, g_Qlo);

    // Weight transpose + stacked split
    {
        dim3 blk(32, 8);
        transpose_split3<<<dim3(DM / 32, DM / 32), blk>>>(Wq, pWc3, DM, DM, 0);
        transpose_split3<<<dim3(256 / 32, DM / 32), blk>>>(Wk, pWc3, DM, 256, 1024);
        transpose_split3<<<dim3(256 / 32, DM / 32), blk>>>(Wv, pWc3, DM, 256, 1280);
        transpose_split3<<<dim3(DM / 32, DM / 32), blk>>>(Wo, pWo3, DM, DM, 0);
    }

    // x -> stacked bf16 [hi|lo|hi]
    split3_rows<<<2048, 256>>>(x, px3, MTOK, DM);

    // QKV projection GEMM -> bf16 hi/lo planes
    cudaFuncSetAttribute(mma_gemm<1>, cudaFuncAttributeMaxDynamicSharedMemorySize, GEMM_SMEM);
    cudaFuncSetAttribute(mma_gemm<0>, cudaFuncAttributeMaxDynamicSharedMemorySize, GEMM_SMEM);
    {
        dim3 g(NQKV / BN, MTOK / BM);
        mma_gemm<1><<<g, 256, GEMM_SMEM>>>(px3, pWc3, nullptr, pQhi, pQlo, MTOK, NQKV, K3);
    }

    // RoPE in place on Q and K planes
    {
        int total = MTOK * 20 * 32;
        rope_kernel<<<(total + 255) / 256, 256>>>(pQhi, pQlo);
    }

    // Flash attention (writes stacked ctx into g_C3)
    {
        cudaFuncSetAttribute(attn_mma,
                             cudaFuncAttributeMaxDynamicSharedMemorySize,
                             ATTN_SMEM);
        dim3 ga(SEQ / 128, NHEAD, BATCH);
        attn_mma<<<ga, 256, ATTN_SMEM>>>(pQhi, pQlo, pC3);
    }

    // Output projection GEMM -> fp32 out
    {
        dim3 g(DM / BN, MTOK / BM);
        mma_gemm<0><<<g, 256, GEMM_SMEM>>>(pC3, pWo3, out, nullptr, nullptr, MTOK, DM, K3);
    }
}